// round 8
// baseline (speedup 1.0000x reference)
#include <cuda_runtime.h>
#include <cuda_bf16.h>
#include <cstdint>

#define N_NODES 100000
#define M_PAD   100096            // 782 * 128
#define D 128
#define K2 256                    // concatenated K
#define N_EDGES 1600000
#define EPS_BN 1e-5f
#define NB 98                     // persistent prep blocks

// ---- scratch (device globals) ----
__device__ __align__(16) __nv_bfloat16 g_Ahi[(size_t)M_PAD * K2];  // [m][k]
__device__ __align__(16) __nv_bfloat16 g_Alo[(size_t)M_PAD * K2];
__device__ __align__(16) __nv_bfloat16 g_Bhi[(size_t)K2 * D];      // [k][n]
__device__ __align__(16) __nv_bfloat16 g_Blo[(size_t)K2 * D];
__device__ __align__(16) float g_h[(size_t)N_NODES * D];
__device__ __align__(16) float g_sum[D];
__device__ __align__(16) float g_sumsq[D];
__device__ __align__(16) float g_scale[D];
__device__ __align__(16) float g_shift[D];
__device__ int g_is64;
__device__ int g_cnt[N_NODES];
__device__ int g_bsum[NB];
__device__ int g_boff[NB];
__device__ int g_start[N_NODES + 1];
__device__ int g_cursor[N_NODES];
__device__ int g_sorted[N_EDGES];
__device__ int g_bar_cnt;
__device__ volatile int g_bar_gen;

__device__ __forceinline__ uint32_t smem_u32(const void* p) {
    uint32_t a;
    asm("{ .reg .u64 t; cvta.to.shared.u64 t, %1; cvt.u32.u64 %0, t; }"
        : "=r"(a) : "l"(p));
    return a;
}

// ======================= prep kernels ==============================
__device__ __forceinline__ void grid_sync() {
    __syncthreads();
    if (threadIdx.x == 0) {
        int gen = g_bar_gen;
        __threadfence();
        int arrived = atomicAdd(&g_bar_cnt, 1);
        if (arrived == NB - 1) {
            g_bar_cnt = 0;
            __threadfence();
            g_bar_gen = gen + 1;
        } else {
            while (g_bar_gen == gen) { }
        }
        __threadfence();
    }
    __syncthreads();
}

// zero + sniff + W split/transpose ([k][n] layout) + A pad-row zeroing
__global__ void zero_kernel(const int* __restrict__ ei_raw,
                            const float* __restrict__ W_root,
                            const float* __restrict__ W_rel) {
    int i = blockIdx.x * blockDim.x + threadIdx.x;
    if (i < N_NODES) g_cnt[i] = 0;
    if (i < D) { g_sum[i] = 0.f; g_sumsq[i] = 0.f; }
    if (i == 0) {
        g_bar_cnt = 0;
        g_bar_gen = 0;
        g_start[N_NODES] = N_EDGES;
    }
    // W -> Bhi/Blo in [k][n] (n contiguous)
    if (i < K2 * D) {
        int k = i >> 7;
        int n = i & 127;
        float w = (k < 128) ? W_rel[(size_t)k * D + n]
                            : W_root[(size_t)(k - 128) * D + n];
        __nv_bfloat16 hi = __float2bfloat16(w);
        __nv_bfloat16 lo = __float2bfloat16(w - __bfloat162float(hi));
        g_Bhi[i] = hi;
        g_Blo[i] = lo;
    }
    // zero A pad rows [N_NODES, M_PAD)
    {
        const size_t pad0 = (size_t)N_NODES * K2;
        const int padN = (M_PAD - N_NODES) * K2;   // 24576
        if (i < padN) {
            g_Ahi[pad0 + i] = __float2bfloat16(0.f);
            g_Alo[pad0 + i] = __float2bfloat16(0.f);
        }
    }
    if (blockIdx.x == 0 && threadIdx.x < 32) {
        int nz = 0;
        #pragma unroll 4
        for (int k = threadIdx.x; k < 2048; k += 32)
            nz += (ei_raw[2 * k + 1] != 0);
        unsigned any = __ballot_sync(0xffffffffu, nz != 0);
        if (threadIdx.x == 0) g_is64 = (any == 0) ? 1 : 0;
    }
}

__global__ __launch_bounds__(1024) void prep_kernel(const void* __restrict__ eiv) {
    const int tid = threadIdx.x;
    const int b   = blockIdx.x;
    const int gt  = b * 1024 + tid;
    const int gstride = NB * 1024;
    const int is64 = g_is64;

    if (is64) {
        const long long* ei = (const long long*)eiv;
        for (int e = gt; e < N_EDGES; e += gstride) {
            int dst = (int)__ldg(&ei[(size_t)N_EDGES + e]);
            if ((unsigned)dst < N_NODES) atomicAdd(&g_cnt[dst], 1);
        }
    } else {
        const int* ei = (const int*)eiv;
        for (int e = gt; e < N_EDGES; e += gstride) {
            int dst = __ldg(&ei[(size_t)N_EDGES + e]);
            if ((unsigned)dst < N_NODES) atomicAdd(&g_cnt[dst], 1);
        }
    }
    grid_sync();

    __shared__ int sh[1024];
    const int i = b * 1024 + tid;
    int v = (i < N_NODES) ? g_cnt[i] : 0;
    sh[tid] = v;
    __syncthreads();
    #pragma unroll
    for (int ofs = 1; ofs < 1024; ofs <<= 1) {
        int t = (tid >= ofs) ? sh[tid - ofs] : 0;
        __syncthreads();
        sh[tid] += t;
        __syncthreads();
    }
    int incl = sh[tid];
    if (tid == 1023) g_bsum[b] = incl;
    grid_sync();

    if (b == 0) {
        __shared__ int sb[128];
        int bv = (tid < NB) ? g_bsum[tid] : 0;
        if (tid < 128) sb[tid] = bv;
        __syncthreads();
        #pragma unroll
        for (int ofs = 1; ofs < 128; ofs <<= 1) {
            int t = (tid < 128 && tid >= ofs) ? sb[tid - ofs] : 0;
            __syncthreads();
            if (tid < 128) sb[tid] += t;
            __syncthreads();
        }
        if (tid < NB) g_boff[tid] = sb[tid] - bv;
    }
    grid_sync();

    if (i < N_NODES) {
        int excl = incl - v + g_boff[b];
        g_start[i]  = excl;
        g_cursor[i] = excl;
    }
    grid_sync();

    if (is64) {
        const long long* ei = (const long long*)eiv;
        for (int e = gt; e < N_EDGES; e += gstride) {
            int src = (int)__ldg(&ei[e]);
            int dst = (int)__ldg(&ei[(size_t)N_EDGES + e]);
            if ((unsigned)src >= N_NODES || (unsigned)dst >= N_NODES) continue;
            int pos = atomicAdd(&g_cursor[dst], 1);
            g_sorted[pos] = src;
        }
    } else {
        const int* ei = (const int*)eiv;
        for (int e = gt; e < N_EDGES; e += gstride) {
            int src = __ldg(&ei[e]);
            int dst = __ldg(&ei[(size_t)N_EDGES + e]);
            if ((unsigned)src >= N_NODES || (unsigned)dst >= N_NODES) continue;
            int pos = atomicAdd(&g_cursor[dst], 1);
            g_sorted[pos] = src;
        }
    }
}

// ---------------------------------------------------------------------------
// gather + bf16 hi/lo conversion.
// ---------------------------------------------------------------------------
__device__ __forceinline__ void emit_bf16(float4 a, __nv_bfloat16* hi_p,
                                          __nv_bfloat16* lo_p) {
    __nv_bfloat162 h0, h1, l0, l1;
    h0.x = __float2bfloat16(a.x); h0.y = __float2bfloat16(a.y);
    h1.x = __float2bfloat16(a.z); h1.y = __float2bfloat16(a.w);
    l0.x = __float2bfloat16(a.x - __bfloat162float(h0.x));
    l0.y = __float2bfloat16(a.y - __bfloat162float(h0.y));
    l1.x = __float2bfloat16(a.z - __bfloat162float(h1.x));
    l1.y = __float2bfloat16(a.w - __bfloat162float(h1.y));
    reinterpret_cast<__nv_bfloat162*>(hi_p)[0] = h0;
    reinterpret_cast<__nv_bfloat162*>(hi_p)[1] = h1;
    reinterpret_cast<__nv_bfloat162*>(lo_p)[0] = l0;
    reinterpret_cast<__nv_bfloat162*>(lo_p)[1] = l1;
}

__global__ void gather_kernel(const float* __restrict__ x) {
    int v = (blockIdx.x * blockDim.x + threadIdx.x) >> 5;
    if (v >= N_NODES) return;
    int lane = threadIdx.x & 31;
    int s = g_start[v];
    int e = g_start[v + 1];

    float4 a0 = {0.f, 0.f, 0.f, 0.f};
    float4 a1 = a0, a2 = a0, a3 = a0;
    int i = s;
    for (; i + 4 <= e; i += 4) {
        int s0 = __ldg(&g_sorted[i]);
        int s1 = __ldg(&g_sorted[i + 1]);
        int s2 = __ldg(&g_sorted[i + 2]);
        int s3 = __ldg(&g_sorted[i + 3]);
        float4 v0 = __ldg(reinterpret_cast<const float4*>(x + (size_t)s0 * D) + lane);
        float4 v1 = __ldg(reinterpret_cast<const float4*>(x + (size_t)s1 * D) + lane);
        float4 v2 = __ldg(reinterpret_cast<const float4*>(x + (size_t)s2 * D) + lane);
        float4 v3 = __ldg(reinterpret_cast<const float4*>(x + (size_t)s3 * D) + lane);
        a0.x += v0.x; a0.y += v0.y; a0.z += v0.z; a0.w += v0.w;
        a1.x += v1.x; a1.y += v1.y; a1.z += v1.z; a1.w += v1.w;
        a2.x += v2.x; a2.y += v2.y; a2.z += v2.z; a2.w += v2.w;
        a3.x += v3.x; a3.y += v3.y; a3.z += v3.z; a3.w += v3.w;
    }
    for (; i < e; ++i) {
        int s0 = __ldg(&g_sorted[i]);
        float4 v0 = __ldg(reinterpret_cast<const float4*>(x + (size_t)s0 * D) + lane);
        a0.x += v0.x; a0.y += v0.y; a0.z += v0.z; a0.w += v0.w;
    }
    a0.x += a1.x + a2.x + a3.x;
    a0.y += a1.y + a2.y + a3.y;
    a0.z += a1.z + a2.z + a3.z;
    a0.w += a1.w + a2.w + a3.w;

    size_t rb = (size_t)v * K2 + lane * 4;
    emit_bf16(a0, g_Ahi + rb, g_Alo + rb);
    float4 xv = __ldg(reinterpret_cast<const float4*>(x + (size_t)v * D) + lane);
    emit_bf16(xv, g_Ahi + rb + 128, g_Alo + rb + 128);
}

// ---------------------------------------------------------------------------
// bf16x3 GEMM via mma.sync.m16n8k16.  128(M) x 128(N) block tile, K=256 in
// two halves.  512 threads = 16 warps in a 4(M) x 4(N) grid, warp tile 32x32.
// B fragments via ldmatrix.x4.trans (2 n-frags per LDSM).  BN stats fused.
// SMEM: A half hi/lo [128][136]b16, B full hi/lo [256][136]b16 ([k][n]).
// ---------------------------------------------------------------------------
#define ASTR 136                        // bf16 per A row (128 + 8 pad)
#define BSTR 136                        // bf16 per B k-row (128 n + 8 pad)
#define SM_A_HI 1024
#define SM_A_LO (SM_A_HI + 128 * ASTR * 2)       // +34816
#define SM_B_HI (SM_A_LO + 128 * ASTR * 2)
#define SM_B_LO (SM_B_HI + 256 * BSTR * 2)       // +69632
#define SMEM_TOTAL (SM_B_LO + 256 * BSTR * 2)    // 209920

__device__ __forceinline__ void ldsm_x4(uint32_t* r, uint32_t addr) {
    asm volatile("ldmatrix.sync.aligned.m8n8.x4.shared.b16 {%0,%1,%2,%3}, [%4];"
                 : "=r"(r[0]), "=r"(r[1]), "=r"(r[2]), "=r"(r[3]) : "r"(addr));
}
__device__ __forceinline__ void ldsm_x4t(uint32_t* r, uint32_t addr) {
    asm volatile("ldmatrix.sync.aligned.m8n8.x4.trans.shared.b16 {%0,%1,%2,%3}, [%4];"
                 : "=r"(r[0]), "=r"(r[1]), "=r"(r[2]), "=r"(r[3]) : "r"(addr));
}
__device__ __forceinline__ void mma_bf16(float* d, const uint32_t* a,
                                         const uint32_t* b) {
    asm volatile("mma.sync.aligned.m16n8k16.row.col.f32.bf16.bf16.f32 "
                 "{%0,%1,%2,%3}, {%4,%5,%6,%7}, {%8,%9}, {%0,%1,%2,%3};"
                 : "+f"(d[0]), "+f"(d[1]), "+f"(d[2]), "+f"(d[3])
                 : "r"(a[0]), "r"(a[1]), "r"(a[2]), "r"(a[3]),
                   "r"(b[0]), "r"(b[1]));
}

__global__ __launch_bounds__(512) void gemm_mma_kernel(
        const float* __restrict__ b_rel) {
    extern __shared__ __align__(16) char smem[];
    __shared__ float s_sum[128], s_sq[128];
    const uint32_t sbase = smem_u32(smem);
    const int tid  = threadIdx.x;
    const int wid  = tid >> 5;
    const int lane = tid & 31;
    const int wm   = wid & 3;          // 0..3 (M), 32 rows each
    const int wn   = wid >> 2;         // 0..3 (N), 32 cols each
    const int m_base = blockIdx.x * 128;

    if (tid < 128) { s_sum[tid] = 0.f; s_sq[tid] = 0.f; }

    // ---- load B (hi+lo, [256 k][128 n]) : 16 uint4 per thread ----
    #pragma unroll
    for (int vv = 0; vv < 2; ++vv) {
        const __nv_bfloat16* src = vv ? g_Blo : g_Bhi;
        char* db = smem + (vv ? SM_B_LO : SM_B_HI);
        #pragma unroll
        for (int it = 0; it < 8; ++it) {
            int u  = tid + it * 512;           // 4096 uint4
            int kr = u >> 4;
            int sg = u & 15;
            uint4 d = *reinterpret_cast<const uint4*>(src + (size_t)kr * D + sg * 8);
            *reinterpret_cast<uint4*>(db + kr * (BSTR * 2) + sg * 16) = d;
        }
    }

    float acc[2][4][4];
    #pragma unroll
    for (int i = 0; i < 2; ++i)
        #pragma unroll
        for (int j = 0; j < 4; ++j)
            #pragma unroll
            for (int q = 0; q < 4; ++q) acc[i][j][q] = 0.f;

    #pragma unroll 1
    for (int h = 0; h < 2; ++h) {
        if (h) __syncthreads();            // all warps done with A half 0
        // ---- load A half (hi+lo, 128 rows x 128 k): 4 uint4/thread each ----
        #pragma unroll
        for (int vv = 0; vv < 2; ++vv) {
            const __nv_bfloat16* src = vv ? g_Alo : g_Ahi;
            char* da = smem + (vv ? SM_A_LO : SM_A_HI);
            #pragma unroll
            for (int it = 0; it < 4; ++it) {
                int u = tid + it * 512;        // 2048 uint4
                int r = u >> 4;
                int sg = u & 15;
                uint4 d = *reinterpret_cast<const uint4*>(
                        src + (size_t)(m_base + r) * K2 + h * 128 + sg * 8);
                *reinterpret_cast<uint4*>(da + r * (ASTR * 2) + sg * 16) = d;
            }
        }
        __syncthreads();

        #pragma unroll 1
        for (int ks = 0; ks < 8; ++ks) {
            const int k0 = ks * 16;
            // A fragments (hi+lo), 2 m-frags of 16 rows
            uint32_t ah[2][4], al[2][4];
            const uint32_t a_lane_off =
                (uint32_t)((lane & 15) * (ASTR * 2) +
                           (k0 + ((lane >> 4) << 3)) * 2);
            #pragma unroll
            for (int fm = 0; fm < 2; ++fm) {
                uint32_t ro = (uint32_t)((wm * 32 + fm * 16) * (ASTR * 2));
                ldsm_x4(ah[fm], sbase + SM_A_HI + ro + a_lane_off);
                ldsm_x4(al[fm], sbase + SM_A_LO + ro + a_lane_off);
            }
            // B fragments via x4.trans: one load covers 2 n-frags (16 cols).
            // lanes 0-15 -> rows (k0..k0+15) at col c0; lanes 16-31 -> col c0+8.
            const uint32_t b_lane_off =
                (uint32_t)((h * 128 + k0 + (lane & 15)) * (BSTR * 2) +
                           ((lane >> 4) << 4));   // +16B = 8 cols for hi half
            uint32_t bh[2][4], bl[2][4];
            #pragma unroll
            for (int fj = 0; fj < 2; ++fj) {
                uint32_t co = (uint32_t)((wn * 32 + fj * 16) * 2);
                ldsm_x4t(bh[fj], sbase + SM_B_HI + b_lane_off + co);
                ldsm_x4t(bl[fj], sbase + SM_B_LO + b_lane_off + co);
            }
            #pragma unroll
            for (int fm = 0; fm < 2; ++fm)
                #pragma unroll
                for (int fn = 0; fn < 4; ++fn) {
                    const uint32_t* pbh = &bh[fn >> 1][(fn & 1) * 2];
                    const uint32_t* pbl = &bl[fn >> 1][(fn & 1) * 2];
                    mma_bf16(acc[fm][fn], ah[fm], pbh);
                    mma_bf16(acc[fm][fn], ah[fm], pbl);
                    mma_bf16(acc[fm][fn], al[fm], pbh);
                }
        }
    }

    // ---- epilogue: +b_rel, store h, BN column stats ----
    float2 br[4];
    #pragma unroll
    for (int fn = 0; fn < 4; ++fn) {
        int c = wn * 32 + fn * 8 + 2 * (lane & 3);
        br[fn].x = __ldg(&b_rel[c]);
        br[fn].y = __ldg(&b_rel[c + 1]);
    }
    float psum[4][2], psq[4][2];
    #pragma unroll
    for (int fn = 0; fn < 4; ++fn) {
        psum[fn][0] = psum[fn][1] = 0.f;
        psq[fn][0]  = psq[fn][1]  = 0.f;
    }

    #pragma unroll
    for (int fm = 0; fm < 2; ++fm) {
        int r0 = m_base + wm * 32 + fm * 16 + (lane >> 2);
        int r1 = r0 + 8;
        bool ok0 = (r0 < N_NODES), ok1 = (r1 < N_NODES);
        #pragma unroll
        for (int fn = 0; fn < 4; ++fn) {
            int c = wn * 32 + fn * 8 + 2 * (lane & 3);
            float h0 = acc[fm][fn][0] + br[fn].x;
            float h1 = acc[fm][fn][1] + br[fn].y;
            float h2 = acc[fm][fn][2] + br[fn].x;
            float h3 = acc[fm][fn][3] + br[fn].y;
            if (ok0) {
                *reinterpret_cast<float2*>(&g_h[(size_t)r0 * D + c]) =
                    make_float2(h0, h1);
                psum[fn][0] += h0; psum[fn][1] += h1;
                psq[fn][0]  += h0 * h0; psq[fn][1] += h1 * h1;
            }
            if (ok1) {
                *reinterpret_cast<float2*>(&g_h[(size_t)r1 * D + c]) =
                    make_float2(h2, h3);
                psum[fn][0] += h2; psum[fn][1] += h3;
                psq[fn][0]  += h2 * h2; psq[fn][1] += h3 * h3;
            }
        }
    }
    #pragma unroll
    for (int fn = 0; fn < 4; ++fn) {
        int c = wn * 32 + fn * 8 + 2 * (lane & 3);
        atomicAdd(&s_sum[c],     psum[fn][0]);
        atomicAdd(&s_sum[c + 1], psum[fn][1]);
        atomicAdd(&s_sq[c],      psq[fn][0]);
        atomicAdd(&s_sq[c + 1],  psq[fn][1]);
    }
    __syncthreads();
    if (tid < 128) {
        atomicAdd(&g_sum[tid],   s_sum[tid]);
        atomicAdd(&g_sumsq[tid], s_sq[tid]);
    }
}

// ---------------------------------------------------------------------------
__global__ void stats_kernel(const float* __restrict__ gamma,
                             const float* __restrict__ beta) {
    int c = threadIdx.x;
    float inv_n = 1.0f / (float)N_NODES;
    float mean = g_sum[c] * inv_n;
    float var  = g_sumsq[c] * inv_n - mean * mean;
    float sc = gamma[c] * rsqrtf(var + EPS_BN);
    g_scale[c] = sc;
    g_shift[c] = beta[c] - mean * sc;
}

__global__ void norm_kernel(float* __restrict__ out) {
    size_t i = (size_t)blockIdx.x * blockDim.x + threadIdx.x;
    const size_t n4 = (size_t)N_NODES * (D / 4);
    if (i >= n4) return;
    int c4 = (int)(i & 31);
    float4 h  = reinterpret_cast<const float4*>(g_h)[i];
    float4 sc = reinterpret_cast<const float4*>(g_scale)[c4];
    float4 sh = reinterpret_cast<const float4*>(g_shift)[c4];
    float4 o;
    o.x = fmaxf(fmaf(h.x, sc.x, sh.x), 0.f);
    o.y = fmaxf(fmaf(h.y, sc.y, sh.y), 0.f);
    o.z = fmaxf(fmaf(h.z, sc.z, sh.z), 0.f);
    o.w = fmaxf(fmaf(h.w, sc.w, sh.w), 0.f);
    reinterpret_cast<float4*>(out)[i] = o;
}

// ---------------------------------------------------------------------------
extern "C" void kernel_launch(void* const* d_in, const int* in_sizes, int n_in,
                              void* d_out, int out_size) {
    const float* x      = (const float*)d_in[0];
    const void*  ei     = d_in[1];
    const float* W_root = (const float*)d_in[2];
    const float* W_rel  = (const float*)d_in[3];
    const float* b_rel  = (const float*)d_in[4];
    const float* gamma  = (const float*)d_in[5];
    const float* beta   = (const float*)d_in[6];
    float*       out    = (float*)d_out;

    (void)in_sizes; (void)n_in; (void)out_size;

    cudaFuncSetAttribute(gemm_mma_kernel,
                         cudaFuncAttributeMaxDynamicSharedMemorySize, SMEM_TOTAL);

    zero_kernel<<<(N_NODES + 255) / 256, 256>>>((const int*)ei, W_root, W_rel); // 1
    prep_kernel<<<NB, 1024>>>(ei);                                              // 2
    gather_kernel<<<(N_NODES * 32 + 255) / 256, 256>>>(x);                      // 3
    gemm_mma_kernel<<<M_PAD / 128, 512, SMEM_TOTAL>>>(b_rel);                   // 4 (profiled)
    stats_kernel<<<1, 128>>>(gamma, beta);                                      // 5
    norm_kernel<<<12500, 256>>>(out);                                           // 6
}

// round 9
// speedup vs baseline: 1.2547x; 1.2547x over previous
#include <cuda_runtime.h>
#include <cuda_bf16.h>
#include <cstdint>

#define N_NODES 100000
#define M_PAD   100096            // 782 * 128
#define D 128
#define K2 256                    // concatenated K
#define N_EDGES 1600000
#define EPS_BN 1e-5f
#define NB 98                     // persistent prep blocks

// ---- scratch (device globals) ----
__device__ __align__(16) __nv_bfloat16 g_Ahi[(size_t)M_PAD * K2];  // [m][k]
__device__ __align__(16) __nv_bfloat16 g_Alo[(size_t)M_PAD * K2];
__device__ __align__(16) __nv_bfloat16 g_Bhi[(size_t)K2 * D];      // [k][n]
__device__ __align__(16) __nv_bfloat16 g_Blo[(size_t)K2 * D];
__device__ __align__(16) float g_h[(size_t)N_NODES * D];
__device__ __align__(16) float g_sum[D];
__device__ __align__(16) float g_sumsq[D];
__device__ __align__(16) float g_scale[D];
__device__ __align__(16) float g_shift[D];
__device__ int g_is64;
__device__ int g_cnt[N_NODES];
__device__ int g_bsum[NB];
__device__ int g_boff[NB];
__device__ int g_start[N_NODES + 1];
__device__ int g_cursor[N_NODES];
__device__ int g_sorted[N_EDGES];
__device__ int g_bar_cnt;
__device__ volatile int g_bar_gen;

__device__ __forceinline__ uint32_t smem_u32(const void* p) {
    uint32_t a;
    asm("{ .reg .u64 t; cvta.to.shared.u64 t, %1; cvt.u32.u64 %0, t; }"
        : "=r"(a) : "l"(p));
    return a;
}

// ======================= prep kernels ==============================
__device__ __forceinline__ void grid_sync() {
    __syncthreads();
    if (threadIdx.x == 0) {
        int gen = g_bar_gen;
        __threadfence();
        int arrived = atomicAdd(&g_bar_cnt, 1);
        if (arrived == NB - 1) {
            g_bar_cnt = 0;
            __threadfence();
            g_bar_gen = gen + 1;
        } else {
            while (g_bar_gen == gen) { }
        }
        __threadfence();
    }
    __syncthreads();
}

// zero + sniff + W split/transpose ([k][n] layout) + A pad-row zeroing
__global__ void zero_kernel(const int* __restrict__ ei_raw,
                            const float* __restrict__ W_root,
                            const float* __restrict__ W_rel) {
    int i = blockIdx.x * blockDim.x + threadIdx.x;
    if (i < N_NODES) g_cnt[i] = 0;
    if (i < D) { g_sum[i] = 0.f; g_sumsq[i] = 0.f; }
    if (i == 0) {
        g_bar_cnt = 0;
        g_bar_gen = 0;
        g_start[N_NODES] = N_EDGES;
    }
    // W -> Bhi/Blo in [k][n] (n contiguous)
    if (i < K2 * D) {
        int k = i >> 7;
        int n = i & 127;
        float w = (k < 128) ? W_rel[(size_t)k * D + n]
                            : W_root[(size_t)(k - 128) * D + n];
        __nv_bfloat16 hi = __float2bfloat16(w);
        __nv_bfloat16 lo = __float2bfloat16(w - __bfloat162float(hi));
        g_Bhi[i] = hi;
        g_Blo[i] = lo;
    }
    // zero A pad rows [N_NODES, M_PAD)
    {
        const size_t pad0 = (size_t)N_NODES * K2;
        const int padN = (M_PAD - N_NODES) * K2;   // 24576
        if (i < padN) {
            g_Ahi[pad0 + i] = __float2bfloat16(0.f);
            g_Alo[pad0 + i] = __float2bfloat16(0.f);
        }
    }
    if (blockIdx.x == 0 && threadIdx.x < 32) {
        int nz = 0;
        #pragma unroll 4
        for (int k = threadIdx.x; k < 2048; k += 32)
            nz += (ei_raw[2 * k + 1] != 0);
        unsigned any = __ballot_sync(0xffffffffu, nz != 0);
        if (threadIdx.x == 0) g_is64 = (any == 0) ? 1 : 0;
    }
}

__global__ __launch_bounds__(1024) void prep_kernel(const void* __restrict__ eiv) {
    const int tid = threadIdx.x;
    const int b   = blockIdx.x;
    const int gt  = b * 1024 + tid;
    const int gstride = NB * 1024;
    const int is64 = g_is64;

    if (is64) {
        const long long* ei = (const long long*)eiv;
        for (int e = gt; e < N_EDGES; e += gstride) {
            int dst = (int)__ldg(&ei[(size_t)N_EDGES + e]);
            if ((unsigned)dst < N_NODES) atomicAdd(&g_cnt[dst], 1);
        }
    } else {
        const int* ei = (const int*)eiv;
        for (int e = gt; e < N_EDGES; e += gstride) {
            int dst = __ldg(&ei[(size_t)N_EDGES + e]);
            if ((unsigned)dst < N_NODES) atomicAdd(&g_cnt[dst], 1);
        }
    }
    grid_sync();

    __shared__ int sh[1024];
    const int i = b * 1024 + tid;
    int v = (i < N_NODES) ? g_cnt[i] : 0;
    sh[tid] = v;
    __syncthreads();
    #pragma unroll
    for (int ofs = 1; ofs < 1024; ofs <<= 1) {
        int t = (tid >= ofs) ? sh[tid - ofs] : 0;
        __syncthreads();
        sh[tid] += t;
        __syncthreads();
    }
    int incl = sh[tid];
    if (tid == 1023) g_bsum[b] = incl;
    grid_sync();

    if (b == 0) {
        __shared__ int sb[128];
        int bv = (tid < NB) ? g_bsum[tid] : 0;
        if (tid < 128) sb[tid] = bv;
        __syncthreads();
        #pragma unroll
        for (int ofs = 1; ofs < 128; ofs <<= 1) {
            int t = (tid < 128 && tid >= ofs) ? sb[tid - ofs] : 0;
            __syncthreads();
            if (tid < 128) sb[tid] += t;
            __syncthreads();
        }
        if (tid < NB) g_boff[tid] = sb[tid] - bv;
    }
    grid_sync();

    if (i < N_NODES) {
        int excl = incl - v + g_boff[b];
        g_start[i]  = excl;
        g_cursor[i] = excl;
    }
    grid_sync();

    if (is64) {
        const long long* ei = (const long long*)eiv;
        for (int e = gt; e < N_EDGES; e += gstride) {
            int src = (int)__ldg(&ei[e]);
            int dst = (int)__ldg(&ei[(size_t)N_EDGES + e]);
            if ((unsigned)src >= N_NODES || (unsigned)dst >= N_NODES) continue;
            int pos = atomicAdd(&g_cursor[dst], 1);
            g_sorted[pos] = src;
        }
    } else {
        const int* ei = (const int*)eiv;
        for (int e = gt; e < N_EDGES; e += gstride) {
            int src = __ldg(&ei[e]);
            int dst = __ldg(&ei[(size_t)N_EDGES + e]);
            if ((unsigned)src >= N_NODES || (unsigned)dst >= N_NODES) continue;
            int pos = atomicAdd(&g_cursor[dst], 1);
            g_sorted[pos] = src;
        }
    }
}

// ---------------------------------------------------------------------------
// gather + bf16 hi/lo conversion.
// ---------------------------------------------------------------------------
__device__ __forceinline__ void emit_bf16(float4 a, __nv_bfloat16* hi_p,
                                          __nv_bfloat16* lo_p) {
    __nv_bfloat162 h0, h1, l0, l1;
    h0.x = __float2bfloat16(a.x); h0.y = __float2bfloat16(a.y);
    h1.x = __float2bfloat16(a.z); h1.y = __float2bfloat16(a.w);
    l0.x = __float2bfloat16(a.x - __bfloat162float(h0.x));
    l0.y = __float2bfloat16(a.y - __bfloat162float(h0.y));
    l1.x = __float2bfloat16(a.z - __bfloat162float(h1.x));
    l1.y = __float2bfloat16(a.w - __bfloat162float(h1.y));
    reinterpret_cast<__nv_bfloat162*>(hi_p)[0] = h0;
    reinterpret_cast<__nv_bfloat162*>(hi_p)[1] = h1;
    reinterpret_cast<__nv_bfloat162*>(lo_p)[0] = l0;
    reinterpret_cast<__nv_bfloat162*>(lo_p)[1] = l1;
}

__global__ void gather_kernel(const float* __restrict__ x) {
    int v = (blockIdx.x * blockDim.x + threadIdx.x) >> 5;
    if (v >= N_NODES) return;
    int lane = threadIdx.x & 31;
    int s = g_start[v];
    int e = g_start[v + 1];

    float4 a0 = {0.f, 0.f, 0.f, 0.f};
    float4 a1 = a0, a2 = a0, a3 = a0;
    int i = s;
    for (; i + 4 <= e; i += 4) {
        int s0 = __ldg(&g_sorted[i]);
        int s1 = __ldg(&g_sorted[i + 1]);
        int s2 = __ldg(&g_sorted[i + 2]);
        int s3 = __ldg(&g_sorted[i + 3]);
        float4 v0 = __ldg(reinterpret_cast<const float4*>(x + (size_t)s0 * D) + lane);
        float4 v1 = __ldg(reinterpret_cast<const float4*>(x + (size_t)s1 * D) + lane);
        float4 v2 = __ldg(reinterpret_cast<const float4*>(x + (size_t)s2 * D) + lane);
        float4 v3 = __ldg(reinterpret_cast<const float4*>(x + (size_t)s3 * D) + lane);
        a0.x += v0.x; a0.y += v0.y; a0.z += v0.z; a0.w += v0.w;
        a1.x += v1.x; a1.y += v1.y; a1.z += v1.z; a1.w += v1.w;
        a2.x += v2.x; a2.y += v2.y; a2.z += v2.z; a2.w += v2.w;
        a3.x += v3.x; a3.y += v3.y; a3.z += v3.z; a3.w += v3.w;
    }
    for (; i < e; ++i) {
        int s0 = __ldg(&g_sorted[i]);
        float4 v0 = __ldg(reinterpret_cast<const float4*>(x + (size_t)s0 * D) + lane);
        a0.x += v0.x; a0.y += v0.y; a0.z += v0.z; a0.w += v0.w;
    }
    a0.x += a1.x + a2.x + a3.x;
    a0.y += a1.y + a2.y + a3.y;
    a0.z += a1.z + a2.z + a3.z;
    a0.w += a1.w + a2.w + a3.w;

    size_t rb = (size_t)v * K2 + lane * 4;
    emit_bf16(a0, g_Ahi + rb, g_Alo + rb);
    float4 xv = __ldg(reinterpret_cast<const float4*>(x + (size_t)v * D) + lane);
    emit_bf16(xv, g_Ahi + rb + 128, g_Alo + rb + 128);
}

// ---------------------------------------------------------------------------
// bf16x3 GEMM via mma.sync.m16n8k16 with a cp.async double-buffered K pipe.
// 128(M) x 128(N) block tile.  256 threads = 8 warps, 2(M) x 4(N) grid,
// warp tile 64x32 (R6 fragment mapping).  K=256 in 8 chunks of BK=32,
// 2-stage cp.async pipeline.  smem 74KB -> 2 blocks/SM.
// ---------------------------------------------------------------------------
#define BK 32
#define ASTR2 40                         // bf16 per A row (32 + 8 pad) = 80B
#define BSTR 136                         // bf16 per B k-row (128 + 8 pad) = 272B
#define A_HI_OFF 0
#define A_LO_OFF 10240                   // 128 * 80
#define B_HI_OFF 20480
#define B_LO_OFF 29184                   // 20480 + 32*272
#define STAGE    37888                   // 29184 + 8704
#define SMEM_TOTAL (2 * STAGE)           // 75776

__device__ __forceinline__ void cpa16(uint32_t dst, const void* src) {
    asm volatile("cp.async.cg.shared.global [%0], [%1], 16;"
                 :: "r"(dst), "l"(src));
}
#define CP_COMMIT() asm volatile("cp.async.commit_group;" ::: "memory")
#define CP_WAIT(n)  asm volatile("cp.async.wait_group %0;" :: "n"(n) : "memory")

__device__ __forceinline__ void ldsm_x4(uint32_t* r, uint32_t addr) {
    asm volatile("ldmatrix.sync.aligned.m8n8.x4.shared.b16 {%0,%1,%2,%3}, [%4];"
                 : "=r"(r[0]), "=r"(r[1]), "=r"(r[2]), "=r"(r[3]) : "r"(addr));
}
__device__ __forceinline__ void ldsm_x4t(uint32_t* r, uint32_t addr) {
    asm volatile("ldmatrix.sync.aligned.m8n8.x4.trans.shared.b16 {%0,%1,%2,%3}, [%4];"
                 : "=r"(r[0]), "=r"(r[1]), "=r"(r[2]), "=r"(r[3]) : "r"(addr));
}
__device__ __forceinline__ void mma_bf16(float* d, const uint32_t* a,
                                         const uint32_t* b) {
    asm volatile("mma.sync.aligned.m16n8k16.row.col.f32.bf16.bf16.f32 "
                 "{%0,%1,%2,%3}, {%4,%5,%6,%7}, {%8,%9}, {%0,%1,%2,%3};"
                 : "+f"(d[0]), "+f"(d[1]), "+f"(d[2]), "+f"(d[3])
                 : "r"(a[0]), "r"(a[1]), "r"(a[2]), "r"(a[3]),
                   "r"(b[0]), "r"(b[1]));
}

__global__ __launch_bounds__(256, 2) void gemm_mma_kernel(
        const float* __restrict__ b_rel) {
    extern __shared__ __align__(16) char smem[];
    __shared__ float s_sum[128], s_sq[128];
    const uint32_t sbase = smem_u32(smem);
    const int tid  = threadIdx.x;
    const int wid  = tid >> 5;
    const int lane = tid & 31;
    const int wm   = wid & 1;          // 0..1 (M), 64 rows
    const int wn   = wid >> 1;         // 0..3 (N), 32 cols
    const int m_base = blockIdx.x * 128;

    if (tid < 128) { s_sum[tid] = 0.f; s_sq[tid] = 0.f; }

    // loader coords (loop-invariant)
    const int ar  = tid >> 2;           // A row for u = tid (r = u>>2)
    const int asg = tid & 3;            // A 16B segment
    const int bkr = tid >> 4;           // B k-row for u = tid
    const int bsg = tid & 15;

    // issue one chunk's cp.async (A hi/lo 2 ea + B hi/lo 2 ea per thread)
    auto issue_chunk = [&](int c, uint32_t st) {
        const int kg = c * BK;
        #pragma unroll
        for (int it = 0; it < 2; ++it) {
            int r  = ar + it * 64;      // u = tid + it*256 -> r = u>>2
            size_t so = (size_t)(m_base + r) * K2 + kg + asg * 8;
            uint32_t dst = sbase + st + r * 80 + asg * 16;
            cpa16(dst + A_HI_OFF, g_Ahi + so);
            cpa16(dst + A_LO_OFF, g_Alo + so);
        }
        #pragma unroll
        for (int it = 0; it < 2; ++it) {
            int kr = bkr + it * 16;     // u = tid + it*256 -> kr = u>>4
            size_t so = (size_t)(kg + kr) * D + bsg * 8;
            uint32_t dst = sbase + st + B_HI_OFF + kr * 272 + bsg * 16;
            cpa16(dst, g_Bhi + so);
            cpa16(dst + (B_LO_OFF - B_HI_OFF), g_Blo + so);
        }
        CP_COMMIT();
    };

    float acc[4][4][4];
    #pragma unroll
    for (int i = 0; i < 4; ++i)
        #pragma unroll
        for (int j = 0; j < 4; ++j)
            #pragma unroll
            for (int q = 0; q < 4; ++q) acc[i][j][q] = 0.f;

    issue_chunk(0, 0);

    #pragma unroll 1
    for (int c = 0; c < 8; ++c) {
        if (c < 7) {
            issue_chunk(c + 1, (uint32_t)(((c + 1) & 1) * STAGE));
            CP_WAIT(1);
        } else {
            CP_WAIT(0);
        }
        __syncthreads();
        const uint32_t st = (uint32_t)((c & 1) * STAGE);

        #pragma unroll
        for (int ks = 0; ks < 2; ++ks) {
            const int k0 = ks * 16;
            // B fragments via x4.trans: lanes 0-15 -> k-rows, +16B col split
            const uint32_t b_lane_off = st + B_HI_OFF +
                (uint32_t)((k0 + (lane & 15)) * 272 + ((lane >> 4) << 4));
            uint32_t bh[2][4], bl[2][4];
            #pragma unroll
            for (int fj = 0; fj < 2; ++fj) {
                uint32_t co = (uint32_t)((wn * 32 + fj * 16) * 2);
                ldsm_x4t(bh[fj], sbase + b_lane_off + co);
                ldsm_x4t(bl[fj], sbase + b_lane_off +
                                 (B_LO_OFF - B_HI_OFF) + co);
            }
            const uint32_t a_lane_off = st +
                (uint32_t)((lane & 15) * 80 + (k0 + ((lane >> 4) << 3)) * 2);
            #pragma unroll
            for (int fm = 0; fm < 4; ++fm) {
                uint32_t ro = (uint32_t)((wm * 64 + fm * 16) * 80);
                uint32_t ah[4], al[4];
                ldsm_x4(ah, sbase + A_HI_OFF + ro + a_lane_off);
                ldsm_x4(al, sbase + A_LO_OFF + ro + a_lane_off);
                #pragma unroll
                for (int fn = 0; fn < 4; ++fn) {
                    const uint32_t* pbh = &bh[fn >> 1][(fn & 1) * 2];
                    const uint32_t* pbl = &bl[fn >> 1][(fn & 1) * 2];
                    mma_bf16(acc[fm][fn], ah, pbh);
                    mma_bf16(acc[fm][fn], ah, pbl);
                    mma_bf16(acc[fm][fn], al, pbh);
                }
            }
        }
        __syncthreads();
    }

    // ---- epilogue: +b_rel, store h, BN column stats ----
    float2 br[4];
    #pragma unroll
    for (int fn = 0; fn < 4; ++fn) {
        int c = wn * 32 + fn * 8 + 2 * (lane & 3);
        br[fn].x = __ldg(&b_rel[c]);
        br[fn].y = __ldg(&b_rel[c + 1]);
    }
    float psum[4][2], psq[4][2];
    #pragma unroll
    for (int fn = 0; fn < 4; ++fn) {
        psum[fn][0] = psum[fn][1] = 0.f;
        psq[fn][0]  = psq[fn][1]  = 0.f;
    }

    #pragma unroll
    for (int fm = 0; fm < 4; ++fm) {
        int r0 = m_base + wm * 64 + fm * 16 + (lane >> 2);
        int r1 = r0 + 8;
        bool ok0 = (r0 < N_NODES), ok1 = (r1 < N_NODES);
        #pragma unroll
        for (int fn = 0; fn < 4; ++fn) {
            int c = wn * 32 + fn * 8 + 2 * (lane & 3);
            float h0 = acc[fm][fn][0] + br[fn].x;
            float h1 = acc[fm][fn][1] + br[fn].y;
            float h2 = acc[fm][fn][2] + br[fn].x;
            float h3 = acc[fm][fn][3] + br[fn].y;
            if (ok0) {
                *reinterpret_cast<float2*>(&g_h[(size_t)r0 * D + c]) =
                    make_float2(h0, h1);
                psum[fn][0] += h0; psum[fn][1] += h1;
                psq[fn][0]  += h0 * h0; psq[fn][1] += h1 * h1;
            }
            if (ok1) {
                *reinterpret_cast<float2*>(&g_h[(size_t)r1 * D + c]) =
                    make_float2(h2, h3);
                psum[fn][0] += h2; psum[fn][1] += h3;
                psq[fn][0]  += h2 * h2; psq[fn][1] += h3 * h3;
            }
        }
    }
    #pragma unroll
    for (int fn = 0; fn < 4; ++fn) {
        int c = wn * 32 + fn * 8 + 2 * (lane & 3);
        atomicAdd(&s_sum[c],     psum[fn][0]);
        atomicAdd(&s_sum[c + 1], psum[fn][1]);
        atomicAdd(&s_sq[c],      psq[fn][0]);
        atomicAdd(&s_sq[c + 1],  psq[fn][1]);
    }
    __syncthreads();
    if (tid < 128) {
        atomicAdd(&g_sum[tid],   s_sum[tid]);
        atomicAdd(&g_sumsq[tid], s_sq[tid]);
    }
}

// ---------------------------------------------------------------------------
__global__ void stats_kernel(const float* __restrict__ gamma,
                             const float* __restrict__ beta) {
    int c = threadIdx.x;
    float inv_n = 1.0f / (float)N_NODES;
    float mean = g_sum[c] * inv_n;
    float var  = g_sumsq[c] * inv_n - mean * mean;
    float sc = gamma[c] * rsqrtf(var + EPS_BN);
    g_scale[c] = sc;
    g_shift[c] = beta[c] - mean * sc;
}

__global__ void norm_kernel(float* __restrict__ out) {
    size_t i = (size_t)blockIdx.x * blockDim.x + threadIdx.x;
    const size_t n4 = (size_t)N_NODES * (D / 4);
    if (i >= n4) return;
    int c4 = (int)(i & 31);
    float4 h  = reinterpret_cast<const float4*>(g_h)[i];
    float4 sc = reinterpret_cast<const float4*>(g_scale)[c4];
    float4 sh = reinterpret_cast<const float4*>(g_shift)[c4];
    float4 o;
    o.x = fmaxf(fmaf(h.x, sc.x, sh.x), 0.f);
    o.y = fmaxf(fmaf(h.y, sc.y, sh.y), 0.f);
    o.z = fmaxf(fmaf(h.z, sc.z, sh.z), 0.f);
    o.w = fmaxf(fmaf(h.w, sc.w, sh.w), 0.f);
    reinterpret_cast<float4*>(out)[i] = o;
}

// ---------------------------------------------------------------------------
extern "C" void kernel_launch(void* const* d_in, const int* in_sizes, int n_in,
                              void* d_out, int out_size) {
    const float* x      = (const float*)d_in[0];
    const void*  ei     = d_in[1];
    const float* W_root = (const float*)d_in[2];
    const float* W_rel  = (const float*)d_in[3];
    const float* b_rel  = (const float*)d_in[4];
    const float* gamma  = (const float*)d_in[5];
    const float* beta   = (const float*)d_in[6];
    float*       out    = (float*)d_out;

    (void)in_sizes; (void)n_in; (void)out_size;

    cudaFuncSetAttribute(gemm_mma_kernel,
                         cudaFuncAttributeMaxDynamicSharedMemorySize, SMEM_TOTAL);

    zero_kernel<<<(N_NODES + 255) / 256, 256>>>((const int*)ei, W_root, W_rel); // 1
    prep_kernel<<<NB, 1024>>>(ei);                                              // 2
    gather_kernel<<<(N_NODES * 32 + 255) / 256, 256>>>(x);                      // 3
    gemm_mma_kernel<<<M_PAD / 128, 256, SMEM_TOTAL>>>(b_rel);                   // 4 (profiled)
    stats_kernel<<<1, 128>>>(gamma, beta);                                      // 5
    norm_kernel<<<12500, 256>>>(out);                                           // 6
}